// round 6
// baseline (speedup 1.0000x reference)
#include <cuda_runtime.h>
#include <cuda_fp16.h>
#include <math.h>

#define NMAX 100000
#define EMAX 1600000

// Scratch (device globals)
__device__ __align__(16) int    g_degi[NMAX];        // in-degree histogram (excl self)
__device__ __align__(16) int    g_start[NMAX + 1];   // CSR offsets
__device__ __align__(16) int    g_cursor[NMAX];      // scatter cursors
__device__ __align__(16) int    g_srcs[EMAX];        // CSR: source node per slot
__device__ __align__(16) int2   g_edge[EMAX];        // decoded (row, col) in original order
__device__ __align__(16) float  g_dinv[NMAX];
__device__ __align__(16) float  g_xn[NMAX * 2];      // dinv * x
__device__ __align__(16) __half g_h2n[NMAX * 32];    // fp16: dinv * (h1 @ W2)
__device__ __align__(16) __half g_na[NMAX * 16];     // fp16: h @ mW1[0:32]
__device__ __align__(16) __half g_nb[NMAX * 16];     // fp16: h @ mW1[32:64]
__device__ int g_i64;

// ---------------------------------------------------------------------------
// zero degree histogram; block 0 probes edge_index dtype (int64 => odd words 0)
__global__ void k_init(const unsigned* __restrict__ ei_raw, int e, int n) {
    if (blockIdx.x == 0) {
        __shared__ int odd_nonzero;
        if (threadIdx.x == 0) odd_nonzero = 0;
        __syncthreads();
        int i = threadIdx.x;
        if (2 * i + 1 < 2 * e) {
            if (ei_raw[2 * i + 1] != 0u) odd_nonzero = 1;
        }
        __syncthreads();
        if (threadIdx.x == 0) g_i64 = odd_nonzero ? 0 : 1;
    }
    int i = blockIdx.x * blockDim.x + threadIdx.x;
    if (i < n) g_degi[i] = 0;
}

// decode edge_index -> int2 ; histogram in-degree
__global__ void k_prep(const void* __restrict__ ei, int e) {
    int i = blockIdx.x * blockDim.x + threadIdx.x;
    if (i >= e) return;
    int r, c;
    if (g_i64) {
        r = (int)(reinterpret_cast<const long long*>(ei)[i]);
        c = (int)(reinterpret_cast<const long long*>(ei)[(size_t)e + i]);
    } else {
        r = reinterpret_cast<const int*>(ei)[i];
        c = reinterpret_cast<const int*>(ei)[(size_t)e + i];
    }
    g_edge[i] = make_int2(r, c);
    atomicAdd(&g_degi[c], 1);
}

// single-block exclusive scan of g_degi -> g_start, g_cursor
__global__ void k_scan(int n) {
    __shared__ int wsum[32];
    __shared__ int carry;
    int lane = threadIdx.x & 31;
    int wid = threadIdx.x >> 5;
    if (threadIdx.x == 0) carry = 0;
    __syncthreads();
    for (int base = 0; base < n; base += 1024) {
        int myc = carry;
        int i = base + (int)threadIdx.x;
        int v = (i < n) ? g_degi[i] : 0;
        int s = v;
#pragma unroll
        for (int o = 1; o < 32; o <<= 1) {
            int t = __shfl_up_sync(0xFFFFFFFFu, s, o);
            if (lane >= o) s += t;
        }
        if (lane == 31) wsum[wid] = s;
        __syncthreads();
        if (wid == 0) {
            int w = wsum[lane];
#pragma unroll
            for (int o = 1; o < 32; o <<= 1) {
                int t = __shfl_up_sync(0xFFFFFFFFu, w, o);
                if (lane >= o) w += t;
            }
            wsum[lane] = w;
        }
        __syncthreads();
        int offset = wid ? wsum[wid - 1] : 0;
        int excl = myc + offset + s - v;
        if (i < n) { g_start[i] = excl; g_cursor[i] = excl; }
        int total = wsum[31];
        __syncthreads();
        if (threadIdx.x == 0) carry = myc + total;
        __syncthreads();
    }
    if (threadIdx.x == 0) g_start[n] = carry;
}

// scatter edges into CSR slots
__global__ void k_scatter(int e) {
    int i = blockIdx.x * blockDim.x + threadIdx.x;
    if (i >= e) return;
    int2 eg = g_edge[i];
    int slot = atomicAdd(&g_cursor[eg.y], 1);
    g_srcs[slot] = eg.x;
}

// dinv = (deg+1)^-1/2 ; xn = dinv * x
__global__ void k_dinv(const float* __restrict__ x, int n) {
    int i = blockIdx.x * blockDim.x + threadIdx.x;
    if (i >= n) return;
    float di = rsqrtf((float)(g_degi[i] + 1));
    g_dinv[i] = di;
    float2 xv = reinterpret_cast<const float2*>(x)[i];
    reinterpret_cast<float2*>(g_xn)[i] = make_float2(di * xv.x, di * xv.y);
}

// layer 1 fused: gather xn over in-edges, v = dinv*(agg + xn_self),
// h1 = relu(v@W1+b1), h2n = fp16(dinv*(h1@W2))
__global__ void k_layer1(const float* __restrict__ W1,  // [2,64]
                         const float* __restrict__ b1,  // [64]
                         const float* __restrict__ W2,  // [64,32]
                         int n) {
    __shared__ float sW1[128];
    __shared__ float sb1[64];
    __shared__ float sW2[2048];
    int t = threadIdx.x;
    for (int i = t; i < 128; i += blockDim.x) sW1[i] = W1[i];
    for (int i = t; i < 64; i += blockDim.x) sb1[i] = b1[i];
    for (int i = t; i < 2048; i += blockDim.x) sW2[i] = W2[i];
    __syncthreads();

    int nn = blockIdx.x * blockDim.x + t;
    if (nn >= n) return;
    int s0 = g_start[nn], s1 = g_start[nn + 1];
    float a0 = 0.0f, a1 = 0.0f;
    for (int j = s0; j < s1; j++) {
        int r = g_srcs[j];
        float2 v = reinterpret_cast<const float2*>(g_xn)[r];
        a0 += v.x; a1 += v.y;
    }
    float di = g_dinv[nn];
    float2 xv = reinterpret_cast<const float2*>(g_xn)[nn];
    float v0 = di * (a0 + xv.x);
    float v1 = di * (a1 + xv.y);

    float acc[32];
#pragma unroll
    for (int k = 0; k < 32; k++) acc[k] = 0.0f;
#pragma unroll 4
    for (int j = 0; j < 64; j++) {
        float h = fmaxf(fmaf(v0, sW1[j], fmaf(v1, sW1[64 + j], sb1[j])), 0.0f);
#pragma unroll
        for (int k = 0; k < 32; k++) acc[k] = fmaf(h, sW2[j * 32 + k], acc[k]);
    }

    __half2 hp[16];
#pragma unroll
    for (int k = 0; k < 16; k++)
        hp[k] = __floats2half2_rn(di * acc[2 * k], di * acc[2 * k + 1]);
    uint4* o = reinterpret_cast<uint4*>(g_h2n + (size_t)nn * 32);
    const uint4* src = reinterpret_cast<const uint4*>(hp);
#pragma unroll
    for (int k = 0; k < 4; k++) o[k] = src[k];
}

// layer 2 fused: gather h2n rows over in-edges + self, h = relu(dinv*agg + b2),
// na = fp16(h@A), nb = fp16(h@B)
__global__ void k_layer2(const float* __restrict__ mW1,  // [65,16]
                         const float* __restrict__ b2,   // [32]
                         int n) {
    __shared__ float sA[512];
    __shared__ float sB[512];
    __shared__ float sb2[32];
    int t = threadIdx.x;
    for (int i = t; i < 512; i += blockDim.x) { sA[i] = mW1[i]; sB[i] = mW1[512 + i]; }
    for (int i = t; i < 32; i += blockDim.x) sb2[i] = b2[i];
    __syncthreads();

    int nn = blockIdx.x * blockDim.x + t;
    if (nn >= n) return;
    int s0 = g_start[nn], s1 = g_start[nn + 1];

    float acc[32];
    {   // self row
        const uint4* ph = reinterpret_cast<const uint4*>(g_h2n + (size_t)nn * 32);
#pragma unroll
        for (int q = 0; q < 4; q++) {
            uint4 raw = ph[q];
            const __half2* hh = reinterpret_cast<const __half2*>(&raw);
#pragma unroll
            for (int k = 0; k < 4; k++) {
                float2 f = __half22float2(hh[k]);
                acc[8 * q + 2 * k] = f.x;
                acc[8 * q + 2 * k + 1] = f.y;
            }
        }
    }
    for (int j = s0; j < s1; j++) {
        int r = g_srcs[j];
        const uint4* ph = reinterpret_cast<const uint4*>(g_h2n + (size_t)r * 32);
        uint4 r0 = ph[0], r1 = ph[1], r2 = ph[2], r3 = ph[3];
        const __half2* h0 = reinterpret_cast<const __half2*>(&r0);
        const __half2* h1 = reinterpret_cast<const __half2*>(&r1);
        const __half2* h2 = reinterpret_cast<const __half2*>(&r2);
        const __half2* h3 = reinterpret_cast<const __half2*>(&r3);
#pragma unroll
        for (int k = 0; k < 4; k++) {
            float2 f = __half22float2(h0[k]);
            acc[2 * k] += f.x; acc[2 * k + 1] += f.y;
        }
#pragma unroll
        for (int k = 0; k < 4; k++) {
            float2 f = __half22float2(h1[k]);
            acc[8 + 2 * k] += f.x; acc[8 + 2 * k + 1] += f.y;
        }
#pragma unroll
        for (int k = 0; k < 4; k++) {
            float2 f = __half22float2(h2[k]);
            acc[16 + 2 * k] += f.x; acc[16 + 2 * k + 1] += f.y;
        }
#pragma unroll
        for (int k = 0; k < 4; k++) {
            float2 f = __half22float2(h3[k]);
            acc[24 + 2 * k] += f.x; acc[24 + 2 * k + 1] += f.y;
        }
    }

    float di = g_dinv[nn];
    float acca[16], accb[16];
#pragma unroll
    for (int i = 0; i < 16; i++) { acca[i] = 0.0f; accb[i] = 0.0f; }
#pragma unroll
    for (int k = 0; k < 32; k++) {
        float h = fmaxf(fmaf(di, acc[k], sb2[k]), 0.0f);
#pragma unroll
        for (int i = 0; i < 16; i++) {
            acca[i] = fmaf(h, sA[k * 16 + i], acca[i]);
            accb[i] = fmaf(h, sB[k * 16 + i], accb[i]);
        }
    }

    __half2 hpa[8], hpb[8];
#pragma unroll
    for (int k = 0; k < 8; k++) {
        hpa[k] = __floats2half2_rn(acca[2 * k], acca[2 * k + 1]);
        hpb[k] = __floats2half2_rn(accb[2 * k], accb[2 * k + 1]);
    }
    uint4* oa = reinterpret_cast<uint4*>(g_na + (size_t)nn * 16);
    uint4* ob = reinterpret_cast<uint4*>(g_nb + (size_t)nn * 16);
    const uint4* sa = reinterpret_cast<const uint4*>(hpa);
    const uint4* sb = reinterpret_cast<const uint4*>(hpb);
    oa[0] = sa[0]; oa[1] = sa[1];
    ob[0] = sb[0]; ob[1] = sb[1];
}

// per edge: hid = relu(na[r] + nb[c] + attr*mW1[64] + mb1); out = sigmoid(hid@mW2 + mb2)
__global__ void k_edge(const float* __restrict__ ea,
                       const float* __restrict__ mW1,
                       const float* __restrict__ mb1,
                       const float* __restrict__ mW2,
                       const float* __restrict__ mb2,
                       float* __restrict__ out, int e) {
    __shared__ float sw64[16], smb1[16], smw2[16];
    __shared__ float smb2;
    int t = threadIdx.x;
    if (t < 16) {
        sw64[t] = mW1[64 * 16 + t];
        smb1[t] = mb1[t];
        smw2[t] = mW2[t];
    }
    if (t == 0) smb2 = mb2[0];
    __syncthreads();

    int i = blockIdx.x * blockDim.x + t;
    if (i >= e) return;
    int2 eg = g_edge[i];
    float attr = ea[i];

    const uint4* pa = reinterpret_cast<const uint4*>(g_na + (size_t)eg.x * 16);
    const uint4* pb = reinterpret_cast<const uint4*>(g_nb + (size_t)eg.y * 16);
    uint4 ra0 = pa[0], ra1 = pa[1];
    uint4 rb0 = pb[0], rb1 = pb[1];

    float s = 0.0f;
    const __half2* ha = reinterpret_cast<const __half2*>(&ra0);
    const __half2* hb = reinterpret_cast<const __half2*>(&rb0);
#pragma unroll
    for (int q = 0; q < 4; q++) {
        float2 av = __half22float2(ha[q]);
        float2 bv = __half22float2(hb[q]);
        float h;
        h = fmaxf(av.x + bv.x + fmaf(attr, sw64[2 * q], smb1[2 * q]), 0.0f);
        s = fmaf(h, smw2[2 * q], s);
        h = fmaxf(av.y + bv.y + fmaf(attr, sw64[2 * q + 1], smb1[2 * q + 1]), 0.0f);
        s = fmaf(h, smw2[2 * q + 1], s);
    }
    const __half2* ha1 = reinterpret_cast<const __half2*>(&ra1);
    const __half2* hb1 = reinterpret_cast<const __half2*>(&rb1);
#pragma unroll
    for (int q = 0; q < 4; q++) {
        float2 av = __half22float2(ha1[q]);
        float2 bv = __half22float2(hb1[q]);
        float h;
        h = fmaxf(av.x + bv.x + fmaf(attr, sw64[8 + 2 * q], smb1[8 + 2 * q]), 0.0f);
        s = fmaf(h, smw2[8 + 2 * q], s);
        h = fmaxf(av.y + bv.y + fmaf(attr, sw64[8 + 2 * q + 1], smb1[8 + 2 * q + 1]), 0.0f);
        s = fmaf(h, smw2[8 + 2 * q + 1], s);
    }
    float z = s + smb2;
    out[i] = 1.0f / (1.0f + __expf(-z));
}

// ---------------------------------------------------------------------------
extern "C" void kernel_launch(void* const* d_in, const int* in_sizes, int n_in,
                              void* d_out, int out_size) {
    const float* x = (const float*)d_in[0];
    const void* ei = d_in[1];
    const float* ea = (const float*)d_in[2];

    int base = (in_sizes[3] == 128) ? 3 : 4;
    const float* W1 = (const float*)d_in[base + 0];
    const float* b1 = (const float*)d_in[base + 1];
    const float* W2 = (const float*)d_in[base + 2];
    const float* b2 = (const float*)d_in[base + 3];
    const float* mW1 = (const float*)d_in[base + 4];
    const float* mb1 = (const float*)d_in[base + 5];
    const float* mW2 = (const float*)d_in[base + 6];
    const float* mb2 = (const float*)d_in[base + 7];

    int n = in_sizes[0] / 2;
    int e = in_sizes[1] / 2;
    float* out = (float*)d_out;

    const int B = 256;
    int gn = (n + B - 1) / B;
    int ge = (e + B - 1) / B;

    k_init<<<gn, B>>>((const unsigned*)ei, e, n);
    k_prep<<<ge, B>>>(ei, e);
    k_scan<<<1, 1024>>>(n);
    k_scatter<<<ge, B>>>(e);
    k_dinv<<<gn, B>>>(x, n);
    k_layer1<<<gn, B>>>(W1, b1, W2, n);
    k_layer2<<<gn, B>>>(mW1, b2, n);
    k_edge<<<ge, B>>>(ea, mW1, mb1, mW2, mb2, out, e);
}

// round 7
// speedup vs baseline: 1.0777x; 1.0777x over previous
#include <cuda_runtime.h>
#include <cuda_fp16.h>
#include <math.h>

#define NMAX 100000
#define EMAX 1600000

// Scratch (device globals)
__device__ __align__(16) int    g_degi[NMAX];        // in-degree histogram (excl self)
__device__ __align__(16) int    g_start[NMAX + 1];   // CSR offsets
__device__ __align__(16) int    g_cursor[NMAX];      // scatter cursors
__device__ __align__(16) int    g_srcs[EMAX];        // CSR: source node per slot
__device__ __align__(16) int2   g_edge[EMAX];        // decoded (row, col), original order
__device__ __align__(16) float  g_dinv[NMAX];
__device__ __align__(16) float  g_xn[NMAX * 2];      // dinv * x
__device__ __align__(16) __half g_h2n[NMAX * 32];    // fp16: dinv * (h1 @ W2)
__device__ __align__(16) __half g_na[NMAX * 16];     // fp16: h @ mW1[0:32]
__device__ __align__(16) __half g_nb[NMAX * 16];     // fp16: h @ mW1[32:64]
__device__ int g_i64;

// ---------------------------------------------------------------------------
// zero degree histogram; block 0 probes edge_index dtype (int64 => odd words 0)
__global__ void k_init(const unsigned* __restrict__ ei_raw, int e, int n) {
    if (blockIdx.x == 0) {
        __shared__ int odd_nonzero;
        if (threadIdx.x == 0) odd_nonzero = 0;
        __syncthreads();
        int i = threadIdx.x;
        if (2 * i + 1 < 2 * e) {
            if (ei_raw[2 * i + 1] != 0u) odd_nonzero = 1;
        }
        __syncthreads();
        if (threadIdx.x == 0) g_i64 = odd_nonzero ? 0 : 1;
    }
    int i = blockIdx.x * blockDim.x + threadIdx.x;
    if (i < n) g_degi[i] = 0;
}

// decode edge_index -> int2 ; histogram in-degree
__global__ void k_prep(const void* __restrict__ ei, int e) {
    int i = blockIdx.x * blockDim.x + threadIdx.x;
    if (i >= e) return;
    int r, c;
    if (g_i64) {
        r = (int)(reinterpret_cast<const long long*>(ei)[i]);
        c = (int)(reinterpret_cast<const long long*>(ei)[(size_t)e + i]);
    } else {
        r = reinterpret_cast<const int*>(ei)[i];
        c = reinterpret_cast<const int*>(ei)[(size_t)e + i];
    }
    g_edge[i] = make_int2(r, c);
    atomicAdd(&g_degi[c], 1);
}

// single-block exclusive scan of g_degi -> g_start, g_cursor
__global__ void k_scan(int n) {
    __shared__ int wsum[32];
    __shared__ int carry;
    int lane = threadIdx.x & 31;
    int wid = threadIdx.x >> 5;
    if (threadIdx.x == 0) carry = 0;
    __syncthreads();
    for (int base = 0; base < n; base += 1024) {
        int myc = carry;
        int i = base + (int)threadIdx.x;
        int v = (i < n) ? g_degi[i] : 0;
        int s = v;
#pragma unroll
        for (int o = 1; o < 32; o <<= 1) {
            int t = __shfl_up_sync(0xFFFFFFFFu, s, o);
            if (lane >= o) s += t;
        }
        if (lane == 31) wsum[wid] = s;
        __syncthreads();
        if (wid == 0) {
            int w = wsum[lane];
#pragma unroll
            for (int o = 1; o < 32; o <<= 1) {
                int t = __shfl_up_sync(0xFFFFFFFFu, w, o);
                if (lane >= o) w += t;
            }
            wsum[lane] = w;
        }
        __syncthreads();
        int offset = wid ? wsum[wid - 1] : 0;
        int excl = myc + offset + s - v;
        if (i < n) { g_start[i] = excl; g_cursor[i] = excl; }
        int total = wsum[31];
        __syncthreads();
        if (threadIdx.x == 0) carry = myc + total;
        __syncthreads();
    }
    if (threadIdx.x == 0) g_start[n] = carry;
}

// scatter edges into CSR slots
__global__ void k_scatter(int e) {
    int i = blockIdx.x * blockDim.x + threadIdx.x;
    if (i >= e) return;
    int2 eg = g_edge[i];
    int slot = atomicAdd(&g_cursor[eg.y], 1);
    g_srcs[slot] = eg.x;
}

// dinv = (deg+1)^-1/2 ; xn = dinv * x
__global__ void k_dinv(const float* __restrict__ x, int n) {
    int i = blockIdx.x * blockDim.x + threadIdx.x;
    if (i >= n) return;
    float di = rsqrtf((float)(g_degi[i] + 1));
    g_dinv[i] = di;
    float2 xv = reinterpret_cast<const float2*>(x)[i];
    reinterpret_cast<float2*>(g_xn)[i] = make_float2(di * xv.x, di * xv.y);
}

// layer 1 fused: gather xn over in-edges, v = dinv*(agg + xn_self),
// h1 = relu(v@W1+b1), h2n = fp16(dinv*(h1@W2))
__global__ void k_layer1(const float* __restrict__ W1,  // [2,64]
                         const float* __restrict__ b1,  // [64]
                         const float* __restrict__ W2,  // [64,32]
                         int n) {
    __shared__ float sW1[128];
    __shared__ float sb1[64];
    __shared__ float sW2[2048];
    int t = threadIdx.x;
    for (int i = t; i < 128; i += blockDim.x) sW1[i] = W1[i];
    for (int i = t; i < 64; i += blockDim.x) sb1[i] = b1[i];
    for (int i = t; i < 2048; i += blockDim.x) sW2[i] = W2[i];
    __syncthreads();

    int nn = blockIdx.x * blockDim.x + t;
    if (nn >= n) return;
    int s0 = g_start[nn], s1 = g_start[nn + 1];
    float a0 = 0.0f, a1 = 0.0f;
    for (int j = s0; j < s1; j++) {
        int r = g_srcs[j];
        float2 v = reinterpret_cast<const float2*>(g_xn)[r];
        a0 += v.x; a1 += v.y;
    }
    float di = g_dinv[nn];
    float2 xv = reinterpret_cast<const float2*>(g_xn)[nn];
    float v0 = di * (a0 + xv.x);
    float v1 = di * (a1 + xv.y);

    float acc[32];
#pragma unroll
    for (int k = 0; k < 32; k++) acc[k] = 0.0f;
#pragma unroll 4
    for (int j = 0; j < 64; j++) {
        float h = fmaxf(fmaf(v0, sW1[j], fmaf(v1, sW1[64 + j], sb1[j])), 0.0f);
#pragma unroll
        for (int k = 0; k < 32; k++) acc[k] = fmaf(h, sW2[j * 32 + k], acc[k]);
    }

    __half2 hp[16];
#pragma unroll
    for (int k = 0; k < 16; k++)
        hp[k] = __floats2half2_rn(di * acc[2 * k], di * acc[2 * k + 1]);
    uint4* o = reinterpret_cast<uint4*>(g_h2n + (size_t)nn * 32);
    const uint4* src = reinterpret_cast<const uint4*>(hp);
#pragma unroll
    for (int k = 0; k < 4; k++) o[k] = src[k];
}

// layer 2 fused, 4 threads per node: thread p gathers 16B slice p of each
// neighbor row (64B coalesced per neighbor across the group), ReLU via smem,
// then each thread computes 8 of the 32 output columns (na|nb) and writes 16B.
__global__ void k_layer2(const float* __restrict__ mW1,  // [65,16]
                         const float* __restrict__ b2,   // [32]
                         int n) {
    __shared__ float sAB[1024];    // [k][i]: i<16 -> A (na), i>=16 -> B (nb)
    __shared__ float sb2[32];
    __shared__ float sh[64 * 32];  // ReLU'd h per local node
    int t = threadIdx.x;
    for (int idx = t; idx < 1024; idx += blockDim.x) {
        int k = idx >> 5, i = idx & 31;
        sAB[idx] = (i < 16) ? mW1[k * 16 + i] : mW1[(32 + k) * 16 + (i - 16)];
    }
    for (int i = t; i < 32; i += blockDim.x) sb2[i] = b2[i];
    __syncthreads();

    int local = t >> 2;                    // 0..63
    int p = t & 3;                         // slice
    int nn = blockIdx.x * 64 + local;
    bool active = (nn < n);

    if (active) {
        int s0 = g_start[nn], s1 = g_start[nn + 1];
        // self slice
        uint4 raw = reinterpret_cast<const uint4*>(g_h2n + (size_t)nn * 32)[p];
        const __half2* hh = reinterpret_cast<const __half2*>(&raw);
        float acc[8];
#pragma unroll
        for (int k = 0; k < 4; k++) {
            float2 f = __half22float2(hh[k]);
            acc[2 * k] = f.x; acc[2 * k + 1] = f.y;
        }
        for (int j = s0; j < s1; j++) {
            int r = g_srcs[j];
            uint4 rw = reinterpret_cast<const uint4*>(g_h2n + (size_t)r * 32)[p];
            const __half2* h2 = reinterpret_cast<const __half2*>(&rw);
#pragma unroll
            for (int k = 0; k < 4; k++) {
                float2 f = __half22float2(h2[k]);
                acc[2 * k] += f.x; acc[2 * k + 1] += f.y;
            }
        }
        float di = g_dinv[nn];
#pragma unroll
        for (int k = 0; k < 8; k++)
            sh[local * 32 + 8 * p + k] = fmaxf(fmaf(di, acc[k], sb2[8 * p + k]), 0.0f);
    }
    __syncthreads();

    if (active) {
        // thread p computes combined output columns [8p, 8p+8)
        float o8[8];
#pragma unroll
        for (int i = 0; i < 8; i++) o8[i] = 0.0f;
        const float* hrow = sh + local * 32;
#pragma unroll 8
        for (int k = 0; k < 32; k++) {
            float h = hrow[k];
            const float* w = sAB + k * 32 + 8 * p;
#pragma unroll
            for (int i = 0; i < 8; i++) o8[i] = fmaf(h, w[i], o8[i]);
        }
        __half2 hp[4];
#pragma unroll
        for (int k = 0; k < 4; k++)
            hp[k] = __floats2half2_rn(o8[2 * k], o8[2 * k + 1]);
        // cols [0,16) -> na, [16,32) -> nb ; each thread owns 8 cols = 16B
        __half* base = (p < 2) ? (g_na + (size_t)nn * 16 + 8 * p)
                               : (g_nb + (size_t)nn * 16 + 8 * (p - 2));
        *reinterpret_cast<uint4*>(base) = *reinterpret_cast<const uint4*>(hp);
    }
}

// per edge: hid = relu(na[r] + nb[c] + attr*mW1[64] + mb1); out = sigmoid(hid@mW2 + mb2)
__global__ void k_edge(const float* __restrict__ ea,
                       const float* __restrict__ mW1,
                       const float* __restrict__ mb1,
                       const float* __restrict__ mW2,
                       const float* __restrict__ mb2,
                       float* __restrict__ out, int e) {
    __shared__ float sw64[16], smb1[16], smw2[16];
    __shared__ float smb2;
    int t = threadIdx.x;
    if (t < 16) {
        sw64[t] = mW1[64 * 16 + t];
        smb1[t] = mb1[t];
        smw2[t] = mW2[t];
    }
    if (t == 0) smb2 = mb2[0];
    __syncthreads();

    int i = blockIdx.x * blockDim.x + t;
    if (i >= e) return;
    int2 eg = g_edge[i];
    float attr = ea[i];

    const uint4* pa = reinterpret_cast<const uint4*>(g_na + (size_t)eg.x * 16);
    const uint4* pb = reinterpret_cast<const uint4*>(g_nb + (size_t)eg.y * 16);
    uint4 ra0 = pa[0], ra1 = pa[1];
    uint4 rb0 = pb[0], rb1 = pb[1];

    float s = 0.0f;
    const __half2* ha = reinterpret_cast<const __half2*>(&ra0);
    const __half2* hb = reinterpret_cast<const __half2*>(&rb0);
#pragma unroll
    for (int q = 0; q < 4; q++) {
        float2 av = __half22float2(ha[q]);
        float2 bv = __half22float2(hb[q]);
        float h;
        h = fmaxf(av.x + bv.x + fmaf(attr, sw64[2 * q], smb1[2 * q]), 0.0f);
        s = fmaf(h, smw2[2 * q], s);
        h = fmaxf(av.y + bv.y + fmaf(attr, sw64[2 * q + 1], smb1[2 * q + 1]), 0.0f);
        s = fmaf(h, smw2[2 * q + 1], s);
    }
    const __half2* ha1 = reinterpret_cast<const __half2*>(&ra1);
    const __half2* hb1 = reinterpret_cast<const __half2*>(&rb1);
#pragma unroll
    for (int q = 0; q < 4; q++) {
        float2 av = __half22float2(ha1[q]);
        float2 bv = __half22float2(hb1[q]);
        float h;
        h = fmaxf(av.x + bv.x + fmaf(attr, sw64[8 + 2 * q], smb1[8 + 2 * q]), 0.0f);
        s = fmaf(h, smw2[8 + 2 * q], s);
        h = fmaxf(av.y + bv.y + fmaf(attr, sw64[8 + 2 * q + 1], smb1[8 + 2 * q + 1]), 0.0f);
        s = fmaf(h, smw2[8 + 2 * q + 1], s);
    }
    float z = s + smb2;
    out[i] = 1.0f / (1.0f + __expf(-z));
}

// ---------------------------------------------------------------------------
extern "C" void kernel_launch(void* const* d_in, const int* in_sizes, int n_in,
                              void* d_out, int out_size) {
    const float* x = (const float*)d_in[0];
    const void* ei = d_in[1];
    const float* ea = (const float*)d_in[2];

    int base = (in_sizes[3] == 128) ? 3 : 4;
    const float* W1 = (const float*)d_in[base + 0];
    const float* b1 = (const float*)d_in[base + 1];
    const float* W2 = (const float*)d_in[base + 2];
    const float* b2 = (const float*)d_in[base + 3];
    const float* mW1 = (const float*)d_in[base + 4];
    const float* mb1 = (const float*)d_in[base + 5];
    const float* mW2 = (const float*)d_in[base + 6];
    const float* mb2 = (const float*)d_in[base + 7];

    int n = in_sizes[0] / 2;
    int e = in_sizes[1] / 2;
    float* out = (float*)d_out;

    const int B = 256;
    int gn = (n + B - 1) / B;
    int ge = (e + B - 1) / B;
    int gn4 = (n + 63) / 64;           // 4 threads per node

    k_init<<<gn, B>>>((const unsigned*)ei, e, n);
    k_prep<<<ge, B>>>(ei, e);
    k_scan<<<1, 1024>>>(n);
    k_scatter<<<ge, B>>>(e);
    k_dinv<<<gn, B>>>(x, n);
    k_layer1<<<gn, B>>>(W1, b1, W2, n);
    k_layer2<<<gn4, B>>>(mW1, b2, n);
    k_edge<<<ge, B>>>(ea, mW1, mb1, mW2, mb2, out, e);
}

// round 8
// speedup vs baseline: 1.5668x; 1.4538x over previous
#include <cuda_runtime.h>
#include <cuda_fp16.h>
#include <math.h>

#define NMAX 100000
#define EMAX 1600000
#define NBLK ((NMAX + 255) / 256)   // 391

// Scratch (device globals)
__device__ __align__(16) int    g_degi[NMAX];
__device__ __align__(16) int    g_start[NMAX + 1];
__device__ __align__(16) int    g_cursor[NMAX];
__device__ __align__(16) int    g_bsum[NBLK + 1];
__device__ __align__(16) int    g_boff[NBLK + 1];
__device__ __align__(16) int    g_srcs[EMAX];
__device__ __align__(16) int2   g_edge[EMAX];
__device__ __align__(16) float  g_dinv[NMAX];
__device__ __align__(16) float  g_xn[NMAX * 2];
__device__ __align__(16) __half g_h2n[NMAX * 32];
__device__ __align__(16) __half g_na[NMAX * 16];
__device__ __align__(16) __half g_nb[NMAX * 16];
__device__ int g_i64;

// ---------------------------------------------------------------------------
__global__ void k_init(const unsigned* __restrict__ ei_raw, int e, int n) {
    if (blockIdx.x == 0) {
        __shared__ int odd_nonzero;
        if (threadIdx.x == 0) odd_nonzero = 0;
        __syncthreads();
        int i = threadIdx.x;
        if (2 * i + 1 < 2 * e) {
            if (ei_raw[2 * i + 1] != 0u) odd_nonzero = 1;
        }
        __syncthreads();
        if (threadIdx.x == 0) g_i64 = odd_nonzero ? 0 : 1;
    }
    int i = blockIdx.x * blockDim.x + threadIdx.x;
    if (i < n) g_degi[i] = 0;
}

// decode edge_index -> int2 ; histogram in-degree
__global__ void k_prep(const void* __restrict__ ei, int e) {
    int i = blockIdx.x * blockDim.x + threadIdx.x;
    if (i >= e) return;
    int r, c;
    if (g_i64) {
        r = (int)(reinterpret_cast<const long long*>(ei)[i]);
        c = (int)(reinterpret_cast<const long long*>(ei)[(size_t)e + i]);
    } else {
        r = reinterpret_cast<const int*>(ei)[i];
        c = reinterpret_cast<const int*>(ei)[(size_t)e + i];
    }
    g_edge[i] = make_int2(r, c);
    atomicAdd(&g_degi[c], 1);
}

// scan phase 1: per-block sums of degi
__global__ void k_scan1(int n) {
    __shared__ int ws[8];
    int lane = threadIdx.x & 31, wid = threadIdx.x >> 5;
    int i = blockIdx.x * 256 + threadIdx.x;
    int v = (i < n) ? g_degi[i] : 0;
#pragma unroll
    for (int o = 16; o > 0; o >>= 1) v += __shfl_down_sync(0xFFFFFFFFu, v, o);
    if (lane == 0) ws[wid] = v;
    __syncthreads();
    if (threadIdx.x == 0) {
        int s = 0;
#pragma unroll
        for (int w = 0; w < 8; w++) s += ws[w];
        g_bsum[blockIdx.x] = s;
    }
}

// scan phase 2: 1-warp exclusive scan of block sums -> g_boff ; total -> g_start[n]
__global__ void k_scan2(int nb, int n) {
    if (threadIdx.x >= 32) return;
    int lane = threadIdx.x;
    int carry = 0;
    for (int base = 0; base < nb; base += 32) {
        int idx = base + lane;
        int v = (idx < nb) ? g_bsum[idx] : 0;
        int s = v;
#pragma unroll
        for (int o = 1; o < 32; o <<= 1) {
            int t = __shfl_up_sync(0xFFFFFFFFu, s, o);
            if (lane >= o) s += t;
        }
        if (idx < nb) g_boff[idx] = carry + s - v;
        carry += __shfl_sync(0xFFFFFFFFu, s, 31);
    }
    if (lane == 0) g_start[n] = carry;
}

// scan phase 3: per-block local exclusive scan + block offset -> start, cursor
__global__ void k_scan3(int n) {
    __shared__ int ws[8];
    int lane = threadIdx.x & 31, wid = threadIdx.x >> 5;
    int i = blockIdx.x * 256 + threadIdx.x;
    int v = (i < n) ? g_degi[i] : 0;
    int s = v;
#pragma unroll
    for (int o = 1; o < 32; o <<= 1) {
        int t = __shfl_up_sync(0xFFFFFFFFu, s, o);
        if (lane >= o) s += t;
    }
    if (lane == 31) ws[wid] = s;
    __syncthreads();
    if (wid == 0 && lane < 8) {
        int w = ws[lane];
#pragma unroll
        for (int o = 1; o < 8; o <<= 1) {
            int t = __shfl_up_sync(0x000000FFu, w, o);
            if (lane >= o) w += t;
        }
        ws[lane] = w;
    }
    __syncthreads();
    int excl = g_boff[blockIdx.x] + (wid ? ws[wid - 1] : 0) + s - v;
    if (i < n) { g_start[i] = excl; g_cursor[i] = excl; }
}

// scatter edges into CSR slots
__global__ void k_scatter(int e) {
    int i = blockIdx.x * blockDim.x + threadIdx.x;
    if (i >= e) return;
    int2 eg = g_edge[i];
    int slot = atomicAdd(&g_cursor[eg.y], 1);
    g_srcs[slot] = eg.x;
}

// dinv = (deg+1)^-1/2 ; xn = dinv * x
__global__ void k_dinv(const float* __restrict__ x, int n) {
    int i = blockIdx.x * blockDim.x + threadIdx.x;
    if (i >= n) return;
    float di = rsqrtf((float)(g_degi[i] + 1));
    g_dinv[i] = di;
    float2 xv = reinterpret_cast<const float2*>(x)[i];
    reinterpret_cast<float2*>(g_xn)[i] = make_float2(di * xv.x, di * xv.y);
}

// layer 1 fused: gather xn (unroll-4, MLP 4), GEMV, write fp16 h2n
__global__ void k_layer1(const float* __restrict__ W1,  // [2,64]
                         const float* __restrict__ b1,  // [64]
                         const float* __restrict__ W2,  // [64,32]
                         int n) {
    __shared__ float sW1[128];
    __shared__ float sb1[64];
    __shared__ float sW2[2048];
    int t = threadIdx.x;
    for (int i = t; i < 128; i += blockDim.x) sW1[i] = W1[i];
    for (int i = t; i < 64; i += blockDim.x) sb1[i] = b1[i];
    for (int i = t; i < 2048; i += blockDim.x) sW2[i] = W2[i];
    __syncthreads();

    int nn = blockIdx.x * blockDim.x + t;
    if (nn >= n) return;
    int s0 = g_start[nn], s1 = g_start[nn + 1];
    float a0 = 0.0f, a1 = 0.0f;
    int j = s0;
    for (; j + 4 <= s1; j += 4) {
        int r0 = g_srcs[j], r1 = g_srcs[j + 1], r2 = g_srcs[j + 2], r3 = g_srcs[j + 3];
        float2 v0 = reinterpret_cast<const float2*>(g_xn)[r0];
        float2 v1 = reinterpret_cast<const float2*>(g_xn)[r1];
        float2 v2 = reinterpret_cast<const float2*>(g_xn)[r2];
        float2 v3 = reinterpret_cast<const float2*>(g_xn)[r3];
        a0 += (v0.x + v1.x) + (v2.x + v3.x);
        a1 += (v0.y + v1.y) + (v2.y + v3.y);
    }
    for (; j < s1; j++) {
        float2 v = reinterpret_cast<const float2*>(g_xn)[g_srcs[j]];
        a0 += v.x; a1 += v.y;
    }
    float di = g_dinv[nn];
    float2 xv = reinterpret_cast<const float2*>(g_xn)[nn];
    float v0 = di * (a0 + xv.x);
    float v1 = di * (a1 + xv.y);

    float acc[32];
#pragma unroll
    for (int k = 0; k < 32; k++) acc[k] = 0.0f;
#pragma unroll 4
    for (int jj = 0; jj < 64; jj++) {
        float h = fmaxf(fmaf(v0, sW1[jj], fmaf(v1, sW1[64 + jj], sb1[jj])), 0.0f);
#pragma unroll
        for (int k = 0; k < 32; k++) acc[k] = fmaf(h, sW2[jj * 32 + k], acc[k]);
    }

    __half2 hp[16];
#pragma unroll
    for (int k = 0; k < 16; k++)
        hp[k] = __floats2half2_rn(di * acc[2 * k], di * acc[2 * k + 1]);
    uint4* o = reinterpret_cast<uint4*>(g_h2n + (size_t)nn * 32);
    const uint4* src = reinterpret_cast<const uint4*>(hp);
#pragma unroll
    for (int k = 0; k < 4; k++) o[k] = src[k];
}

__device__ __forceinline__ void acc_slice(float* acc, uint4 raw) {
    const __half2* hh = reinterpret_cast<const __half2*>(&raw);
#pragma unroll
    for (int k = 0; k < 4; k++) {
        float2 f = __half22float2(hh[k]);
        acc[2 * k] += f.x; acc[2 * k + 1] += f.y;
    }
}

// layer 2 fused, 4 threads/node, gather unroll-2
__global__ void k_layer2(const float* __restrict__ mW1,  // [65,16]
                         const float* __restrict__ b2,   // [32]
                         int n) {
    __shared__ float sAB[1024];    // [k][i]: i<16 -> A, i>=16 -> B
    __shared__ float sb2[32];
    __shared__ float sh[64 * 32];
    int t = threadIdx.x;
    for (int idx = t; idx < 1024; idx += blockDim.x) {
        int k = idx >> 5, i = idx & 31;
        sAB[idx] = (i < 16) ? mW1[k * 16 + i] : mW1[(32 + k) * 16 + (i - 16)];
    }
    for (int i = t; i < 32; i += blockDim.x) sb2[i] = b2[i];
    __syncthreads();

    int local = t >> 2;
    int p = t & 3;
    int nn = blockIdx.x * 64 + local;
    bool active = (nn < n);

    if (active) {
        int s0 = g_start[nn], s1 = g_start[nn + 1];
        float acc[8];
        {
            uint4 raw = reinterpret_cast<const uint4*>(g_h2n + (size_t)nn * 32)[p];
            const __half2* hh = reinterpret_cast<const __half2*>(&raw);
#pragma unroll
            for (int k = 0; k < 4; k++) {
                float2 f = __half22float2(hh[k]);
                acc[2 * k] = f.x; acc[2 * k + 1] = f.y;
            }
        }
        int j = s0;
        for (; j + 2 <= s1; j += 2) {
            int r0 = g_srcs[j], r1 = g_srcs[j + 1];
            uint4 w0 = reinterpret_cast<const uint4*>(g_h2n + (size_t)r0 * 32)[p];
            uint4 w1 = reinterpret_cast<const uint4*>(g_h2n + (size_t)r1 * 32)[p];
            acc_slice(acc, w0);
            acc_slice(acc, w1);
        }
        if (j < s1) {
            int r0 = g_srcs[j];
            acc_slice(acc, reinterpret_cast<const uint4*>(g_h2n + (size_t)r0 * 32)[p]);
        }
        float di = g_dinv[nn];
#pragma unroll
        for (int k = 0; k < 8; k++)
            sh[local * 32 + 8 * p + k] = fmaxf(fmaf(di, acc[k], sb2[8 * p + k]), 0.0f);
    }
    __syncthreads();

    if (active) {
        float o8[8];
#pragma unroll
        for (int i = 0; i < 8; i++) o8[i] = 0.0f;
        const float* hrow = sh + local * 32;
#pragma unroll 8
        for (int k = 0; k < 32; k++) {
            float h = hrow[k];
            const float* w = sAB + k * 32 + 8 * p;
#pragma unroll
            for (int i = 0; i < 8; i++) o8[i] = fmaf(h, w[i], o8[i]);
        }
        __half2 hp[4];
#pragma unroll
        for (int k = 0; k < 4; k++)
            hp[k] = __floats2half2_rn(o8[2 * k], o8[2 * k + 1]);
        __half* base = (p < 2) ? (g_na + (size_t)nn * 16 + 8 * p)
                               : (g_nb + (size_t)nn * 16 + 8 * (p - 2));
        *reinterpret_cast<uint4*>(base) = *reinterpret_cast<const uint4*>(hp);
    }
}

// per edge: hid = relu(na[r] + nb[c] + attr*mW1[64] + mb1); out = sigmoid(hid@mW2 + mb2)
__global__ void k_edge(const float* __restrict__ ea,
                       const float* __restrict__ mW1,
                       const float* __restrict__ mb1,
                       const float* __restrict__ mW2,
                       const float* __restrict__ mb2,
                       float* __restrict__ out, int e) {
    __shared__ float sw64[16], smb1[16], smw2[16];
    __shared__ float smb2;
    int t = threadIdx.x;
    if (t < 16) {
        sw64[t] = mW1[64 * 16 + t];
        smb1[t] = mb1[t];
        smw2[t] = mW2[t];
    }
    if (t == 0) smb2 = mb2[0];
    __syncthreads();

    int i = blockIdx.x * blockDim.x + t;
    if (i >= e) return;
    int2 eg = g_edge[i];
    float attr = ea[i];

    const uint4* pa = reinterpret_cast<const uint4*>(g_na + (size_t)eg.x * 16);
    const uint4* pb = reinterpret_cast<const uint4*>(g_nb + (size_t)eg.y * 16);
    uint4 ra0 = pa[0], ra1 = pa[1];
    uint4 rb0 = pb[0], rb1 = pb[1];

    float s = 0.0f;
    const __half2* ha = reinterpret_cast<const __half2*>(&ra0);
    const __half2* hb = reinterpret_cast<const __half2*>(&rb0);
#pragma unroll
    for (int q = 0; q < 4; q++) {
        float2 av = __half22float2(ha[q]);
        float2 bv = __half22float2(hb[q]);
        float h;
        h = fmaxf(av.x + bv.x + fmaf(attr, sw64[2 * q], smb1[2 * q]), 0.0f);
        s = fmaf(h, smw2[2 * q], s);
        h = fmaxf(av.y + bv.y + fmaf(attr, sw64[2 * q + 1], smb1[2 * q + 1]), 0.0f);
        s = fmaf(h, smw2[2 * q + 1], s);
    }
    const __half2* ha1 = reinterpret_cast<const __half2*>(&ra1);
    const __half2* hb1 = reinterpret_cast<const __half2*>(&rb1);
#pragma unroll
    for (int q = 0; q < 4; q++) {
        float2 av = __half22float2(ha1[q]);
        float2 bv = __half22float2(hb1[q]);
        float h;
        h = fmaxf(av.x + bv.x + fmaf(attr, sw64[8 + 2 * q], smb1[8 + 2 * q]), 0.0f);
        s = fmaf(h, smw2[8 + 2 * q], s);
        h = fmaxf(av.y + bv.y + fmaf(attr, sw64[8 + 2 * q + 1], smb1[8 + 2 * q + 1]), 0.0f);
        s = fmaf(h, smw2[8 + 2 * q + 1], s);
    }
    float z = s + smb2;
    out[i] = 1.0f / (1.0f + __expf(-z));
}

// ---------------------------------------------------------------------------
extern "C" void kernel_launch(void* const* d_in, const int* in_sizes, int n_in,
                              void* d_out, int out_size) {
    const float* x = (const float*)d_in[0];
    const void* ei = d_in[1];
    const float* ea = (const float*)d_in[2];

    int base = (in_sizes[3] == 128) ? 3 : 4;
    const float* W1 = (const float*)d_in[base + 0];
    const float* b1 = (const float*)d_in[base + 1];
    const float* W2 = (const float*)d_in[base + 2];
    const float* b2 = (const float*)d_in[base + 3];
    const float* mW1 = (const float*)d_in[base + 4];
    const float* mb1 = (const float*)d_in[base + 5];
    const float* mW2 = (const float*)d_in[base + 6];
    const float* mb2 = (const float*)d_in[base + 7];

    int n = in_sizes[0] / 2;
    int e = in_sizes[1] / 2;
    float* out = (float*)d_out;

    const int B = 256;
    int gn = (n + B - 1) / B;
    int ge = (e + B - 1) / B;
    int gn4 = (n + 63) / 64;

    k_init<<<gn, B>>>((const unsigned*)ei, e, n);
    k_prep<<<ge, B>>>(ei, e);
    k_scan1<<<gn, B>>>(n);
    k_scan2<<<1, 32>>>(gn, n);
    k_scan3<<<gn, B>>>(n);
    k_scatter<<<ge, B>>>(e);
    k_dinv<<<gn, B>>>(x, n);
    k_layer1<<<gn, B>>>(W1, b1, W2, n);
    k_layer2<<<gn4, B>>>(mW1, b2, n);
    k_edge<<<ge, B>>>(ea, mW1, mb1, mW2, mb2, out, e);
}

// round 9
// speedup vs baseline: 1.5985x; 1.0202x over previous
#include <cuda_runtime.h>
#include <cuda_fp16.h>
#include <math.h>

#define NMAX 100000
#define EMAX 1600000
#define NBLK ((NMAX + 255) / 256)   // 391 <= 512

// Scratch (device globals)
__device__ __align__(16) int    g_degi[NMAX];
__device__ __align__(16) int    g_start[NMAX + 1];
__device__ __align__(16) int    g_cursor[NMAX];
__device__ __align__(16) int    g_bsum[NBLK + 1];
__device__ __align__(16) int    g_boff[NBLK + 1];
__device__ __align__(16) int    g_srcs[EMAX];
__device__ __align__(16) int2   g_edge[EMAX];
__device__ __align__(16) float  g_dinv[NMAX];
__device__ __align__(16) float  g_xn[NMAX * 2];
__device__ __align__(16) __half g_h2n[NMAX * 32];
__device__ __align__(16) __half g_na[NMAX * 16];
__device__ __align__(16) __half g_nb[NMAX * 16];
__device__ int g_i64;

// ---------------------------------------------------------------------------
__global__ void k_init(const unsigned* __restrict__ ei_raw, int e, int n) {
    if (blockIdx.x == 0) {
        __shared__ int odd_nonzero;
        if (threadIdx.x == 0) odd_nonzero = 0;
        __syncthreads();
        int i = threadIdx.x;
        if (2 * i + 1 < 2 * e) {
            if (ei_raw[2 * i + 1] != 0u) odd_nonzero = 1;
        }
        __syncthreads();
        if (threadIdx.x == 0) g_i64 = odd_nonzero ? 0 : 1;
    }
    int i = blockIdx.x * blockDim.x + threadIdx.x;
    if (i < n) g_degi[i] = 0;
}

// decode edge_index -> int2 ; histogram in-degree
__global__ void k_prep(const void* __restrict__ ei, int e) {
    int i = blockIdx.x * blockDim.x + threadIdx.x;
    if (i >= e) return;
    int r, c;
    if (g_i64) {
        r = (int)(reinterpret_cast<const long long*>(ei)[i]);
        c = (int)(reinterpret_cast<const long long*>(ei)[(size_t)e + i]);
    } else {
        r = reinterpret_cast<const int*>(ei)[i];
        c = reinterpret_cast<const int*>(ei)[(size_t)e + i];
    }
    g_edge[i] = make_int2(r, c);
    atomicAdd(&g_degi[c], 1);
}

// scan phase 1: per-block sums of degi
__global__ void k_scan1(int n) {
    __shared__ int ws[8];
    int lane = threadIdx.x & 31, wid = threadIdx.x >> 5;
    int i = blockIdx.x * 256 + threadIdx.x;
    int v = (i < n) ? g_degi[i] : 0;
#pragma unroll
    for (int o = 16; o > 0; o >>= 1) v += __shfl_down_sync(0xFFFFFFFFu, v, o);
    if (lane == 0) ws[wid] = v;
    __syncthreads();
    if (threadIdx.x == 0) {
        int s = 0;
#pragma unroll
        for (int w = 0; w < 8; w++) s += ws[w];
        g_bsum[blockIdx.x] = s;
    }
}

// scan phase 2: single 512-thread block, one parallel load round,
// two-level (warp + smem) exclusive scan of nb block sums.
__global__ void k_scan2(int nb, int n) {
    __shared__ int ws[16];
    int t = threadIdx.x;           // 0..511
    int lane = t & 31, wid = t >> 5;
    int v = (t < nb) ? g_bsum[t] : 0;
    int s = v;
#pragma unroll
    for (int o = 1; o < 32; o <<= 1) {
        int u = __shfl_up_sync(0xFFFFFFFFu, s, o);
        if (lane >= o) s += u;
    }
    if (lane == 31) ws[wid] = s;
    __syncthreads();
    if (wid == 0 && lane < 16) {
        int w = ws[lane];
#pragma unroll
        for (int o = 1; o < 16; o <<= 1) {
            int u = __shfl_up_sync(0x0000FFFFu, w, o);
            if (lane >= o) w += u;
        }
        ws[lane] = w;
    }
    __syncthreads();
    int excl = (wid ? ws[wid - 1] : 0) + s - v;
    if (t < nb) g_boff[t] = excl;
    if (t == nb - 1) g_start[n] = excl + v;
}

// scan phase 3 + dinv fused: per-block local scan + block offset -> start/cursor;
// also dinv = (deg+1)^-1/2 and xn = dinv * x.
__global__ void k_scan3(const float* __restrict__ x, int n) {
    __shared__ int ws[8];
    int lane = threadIdx.x & 31, wid = threadIdx.x >> 5;
    int i = blockIdx.x * 256 + threadIdx.x;
    int v = (i < n) ? g_degi[i] : 0;
    int s = v;
#pragma unroll
    for (int o = 1; o < 32; o <<= 1) {
        int t = __shfl_up_sync(0xFFFFFFFFu, s, o);
        if (lane >= o) s += t;
    }
    if (lane == 31) ws[wid] = s;
    __syncthreads();
    if (wid == 0 && lane < 8) {
        int w = ws[lane];
#pragma unroll
        for (int o = 1; o < 8; o <<= 1) {
            int t = __shfl_up_sync(0x000000FFu, w, o);
            if (lane >= o) w += t;
        }
        ws[lane] = w;
    }
    __syncthreads();
    int excl = g_boff[blockIdx.x] + (wid ? ws[wid - 1] : 0) + s - v;
    if (i < n) {
        g_start[i] = excl;
        g_cursor[i] = excl;
        float di = rsqrtf((float)(v + 1));
        g_dinv[i] = di;
        float2 xv = reinterpret_cast<const float2*>(x)[i];
        reinterpret_cast<float2*>(g_xn)[i] = make_float2(di * xv.x, di * xv.y);
    }
}

// scatter edges into CSR slots
__global__ void k_scatter(int e) {
    int i = blockIdx.x * blockDim.x + threadIdx.x;
    if (i >= e) return;
    int2 eg = g_edge[i];
    int slot = atomicAdd(&g_cursor[eg.y], 1);
    g_srcs[slot] = eg.x;
}

// layer 1 fused: gather xn (unroll-4), GEMV, write fp16 h2n
__global__ void k_layer1(const float* __restrict__ W1,  // [2,64]
                         const float* __restrict__ b1,  // [64]
                         const float* __restrict__ W2,  // [64,32]
                         int n) {
    __shared__ float sW1[128];
    __shared__ float sb1[64];
    __shared__ float sW2[2048];
    int t = threadIdx.x;
    for (int i = t; i < 128; i += blockDim.x) sW1[i] = W1[i];
    for (int i = t; i < 64; i += blockDim.x) sb1[i] = b1[i];
    for (int i = t; i < 2048; i += blockDim.x) sW2[i] = W2[i];
    __syncthreads();

    int nn = blockIdx.x * blockDim.x + t;
    if (nn >= n) return;
    int s0 = g_start[nn], s1 = g_start[nn + 1];
    float a0 = 0.0f, a1 = 0.0f;
    int j = s0;
    for (; j + 4 <= s1; j += 4) {
        int r0 = g_srcs[j], r1 = g_srcs[j + 1], r2 = g_srcs[j + 2], r3 = g_srcs[j + 3];
        float2 v0 = reinterpret_cast<const float2*>(g_xn)[r0];
        float2 v1 = reinterpret_cast<const float2*>(g_xn)[r1];
        float2 v2 = reinterpret_cast<const float2*>(g_xn)[r2];
        float2 v3 = reinterpret_cast<const float2*>(g_xn)[r3];
        a0 += (v0.x + v1.x) + (v2.x + v3.x);
        a1 += (v0.y + v1.y) + (v2.y + v3.y);
    }
    for (; j < s1; j++) {
        float2 v = reinterpret_cast<const float2*>(g_xn)[g_srcs[j]];
        a0 += v.x; a1 += v.y;
    }
    float di = g_dinv[nn];
    float2 xv = reinterpret_cast<const float2*>(g_xn)[nn];
    float v0 = di * (a0 + xv.x);
    float v1 = di * (a1 + xv.y);

    float acc[32];
#pragma unroll
    for (int k = 0; k < 32; k++) acc[k] = 0.0f;
#pragma unroll 4
    for (int jj = 0; jj < 64; jj++) {
        float h = fmaxf(fmaf(v0, sW1[jj], fmaf(v1, sW1[64 + jj], sb1[jj])), 0.0f);
#pragma unroll
        for (int k = 0; k < 32; k++) acc[k] = fmaf(h, sW2[jj * 32 + k], acc[k]);
    }

    __half2 hp[16];
#pragma unroll
    for (int k = 0; k < 16; k++)
        hp[k] = __floats2half2_rn(di * acc[2 * k], di * acc[2 * k + 1]);
    uint4* o = reinterpret_cast<uint4*>(g_h2n + (size_t)nn * 32);
    const uint4* src = reinterpret_cast<const uint4*>(hp);
#pragma unroll
    for (int k = 0; k < 4; k++) o[k] = src[k];
}

__device__ __forceinline__ void acc_slice(float* acc, uint4 raw) {
    const __half2* hh = reinterpret_cast<const __half2*>(&raw);
#pragma unroll
    for (int k = 0; k < 4; k++) {
        float2 f = __half22float2(hh[k]);
        acc[2 * k] += f.x; acc[2 * k + 1] += f.y;
    }
}

// layer 2 fused, 4 threads/node, gather unroll-2
__global__ void k_layer2(const float* __restrict__ mW1,  // [65,16]
                         const float* __restrict__ b2,   // [32]
                         int n) {
    __shared__ float sAB[1024];    // [k][i]: i<16 -> A, i>=16 -> B
    __shared__ float sb2[32];
    __shared__ float sh[64 * 32];
    int t = threadIdx.x;
    for (int idx = t; idx < 1024; idx += blockDim.x) {
        int k = idx >> 5, i = idx & 31;
        sAB[idx] = (i < 16) ? mW1[k * 16 + i] : mW1[(32 + k) * 16 + (i - 16)];
    }
    for (int i = t; i < 32; i += blockDim.x) sb2[i] = b2[i];
    __syncthreads();

    int local = t >> 2;
    int p = t & 3;
    int nn = blockIdx.x * 64 + local;
    bool active = (nn < n);

    if (active) {
        int s0 = g_start[nn], s1 = g_start[nn + 1];
        float acc[8];
        {
            uint4 raw = reinterpret_cast<const uint4*>(g_h2n + (size_t)nn * 32)[p];
            const __half2* hh = reinterpret_cast<const __half2*>(&raw);
#pragma unroll
            for (int k = 0; k < 4; k++) {
                float2 f = __half22float2(hh[k]);
                acc[2 * k] = f.x; acc[2 * k + 1] = f.y;
            }
        }
        int j = s0;
        for (; j + 2 <= s1; j += 2) {
            int r0 = g_srcs[j], r1 = g_srcs[j + 1];
            uint4 w0 = reinterpret_cast<const uint4*>(g_h2n + (size_t)r0 * 32)[p];
            uint4 w1 = reinterpret_cast<const uint4*>(g_h2n + (size_t)r1 * 32)[p];
            acc_slice(acc, w0);
            acc_slice(acc, w1);
        }
        if (j < s1) {
            int r0 = g_srcs[j];
            acc_slice(acc, reinterpret_cast<const uint4*>(g_h2n + (size_t)r0 * 32)[p]);
        }
        float di = g_dinv[nn];
#pragma unroll
        for (int k = 0; k < 8; k++)
            sh[local * 32 + 8 * p + k] = fmaxf(fmaf(di, acc[k], sb2[8 * p + k]), 0.0f);
    }
    __syncthreads();

    if (active) {
        float o8[8];
#pragma unroll
        for (int i = 0; i < 8; i++) o8[i] = 0.0f;
        const float* hrow = sh + local * 32;
#pragma unroll 8
        for (int k = 0; k < 32; k++) {
            float h = hrow[k];
            const float* w = sAB + k * 32 + 8 * p;
#pragma unroll
            for (int i = 0; i < 8; i++) o8[i] = fmaf(h, w[i], o8[i]);
        }
        __half2 hp[4];
#pragma unroll
        for (int k = 0; k < 4; k++)
            hp[k] = __floats2half2_rn(o8[2 * k], o8[2 * k + 1]);
        __half* base = (p < 2) ? (g_na + (size_t)nn * 16 + 8 * p)
                               : (g_nb + (size_t)nn * 16 + 8 * (p - 2));
        *reinterpret_cast<uint4*>(base) = *reinterpret_cast<const uint4*>(hp);
    }
}

// per edge: hid = relu(na[r] + nb[c] + attr*mW1[64] + mb1); out = sigmoid(hid@mW2 + mb2)
__global__ void k_edge(const float* __restrict__ ea,
                       const float* __restrict__ mW1,
                       const float* __restrict__ mb1,
                       const float* __restrict__ mW2,
                       const float* __restrict__ mb2,
                       float* __restrict__ out, int e) {
    __shared__ float sw64[16], smb1[16], smw2[16];
    __shared__ float smb2;
    int t = threadIdx.x;
    if (t < 16) {
        sw64[t] = mW1[64 * 16 + t];
        smb1[t] = mb1[t];
        smw2[t] = mW2[t];
    }
    if (t == 0) smb2 = mb2[0];
    __syncthreads();

    int i = blockIdx.x * blockDim.x + t;
    if (i >= e) return;
    int2 eg = g_edge[i];
    float attr = ea[i];

    const uint4* pa = reinterpret_cast<const uint4*>(g_na + (size_t)eg.x * 16);
    const uint4* pb = reinterpret_cast<const uint4*>(g_nb + (size_t)eg.y * 16);
    uint4 ra0 = pa[0], ra1 = pa[1];
    uint4 rb0 = pb[0], rb1 = pb[1];

    float s = 0.0f;
    const __half2* ha = reinterpret_cast<const __half2*>(&ra0);
    const __half2* hb = reinterpret_cast<const __half2*>(&rb0);
#pragma unroll
    for (int q = 0; q < 4; q++) {
        float2 av = __half22float2(ha[q]);
        float2 bv = __half22float2(hb[q]);
        float h;
        h = fmaxf(av.x + bv.x + fmaf(attr, sw64[2 * q], smb1[2 * q]), 0.0f);
        s = fmaf(h, smw2[2 * q], s);
        h = fmaxf(av.y + bv.y + fmaf(attr, sw64[2 * q + 1], smb1[2 * q + 1]), 0.0f);
        s = fmaf(h, smw2[2 * q + 1], s);
    }
    const __half2* ha1 = reinterpret_cast<const __half2*>(&ra1);
    const __half2* hb1 = reinterpret_cast<const __half2*>(&rb1);
#pragma unroll
    for (int q = 0; q < 4; q++) {
        float2 av = __half22float2(ha1[q]);
        float2 bv = __half22float2(hb1[q]);
        float h;
        h = fmaxf(av.x + bv.x + fmaf(attr, sw64[8 + 2 * q], smb1[8 + 2 * q]), 0.0f);
        s = fmaf(h, smw2[8 + 2 * q], s);
        h = fmaxf(av.y + bv.y + fmaf(attr, sw64[8 + 2 * q + 1], smb1[8 + 2 * q + 1]), 0.0f);
        s = fmaf(h, smw2[8 + 2 * q + 1], s);
    }
    float z = s + smb2;
    out[i] = 1.0f / (1.0f + __expf(-z));
}

// ---------------------------------------------------------------------------
extern "C" void kernel_launch(void* const* d_in, const int* in_sizes, int n_in,
                              void* d_out, int out_size) {
    const float* x = (const float*)d_in[0];
    const void* ei = d_in[1];
    const float* ea = (const float*)d_in[2];

    int base = (in_sizes[3] == 128) ? 3 : 4;
    const float* W1 = (const float*)d_in[base + 0];
    const float* b1 = (const float*)d_in[base + 1];
    const float* W2 = (const float*)d_in[base + 2];
    const float* b2 = (const float*)d_in[base + 3];
    const float* mW1 = (const float*)d_in[base + 4];
    const float* mb1 = (const float*)d_in[base + 5];
    const float* mW2 = (const float*)d_in[base + 6];
    const float* mb2 = (const float*)d_in[base + 7];

    int n = in_sizes[0] / 2;
    int e = in_sizes[1] / 2;
    float* out = (float*)d_out;

    const int B = 256;
    int gn = (n + B - 1) / B;
    int ge = (e + B - 1) / B;
    int gn4 = (n + 63) / 64;

    k_init<<<gn, B>>>((const unsigned*)ei, e, n);
    k_prep<<<ge, B>>>(ei, e);
    k_scan1<<<gn, B>>>(n);
    k_scan2<<<1, 512>>>(gn, n);
    k_scan3<<<gn, B>>>(x, n);
    k_scatter<<<ge, B>>>(e);
    k_layer1<<<gn, B>>>(W1, b1, W2, n);
    k_layer2<<<gn4, B>>>(mW1, b2, n);
    k_edge<<<ge, B>>>(ea, mW1, mb1, mW2, mb2, out, e);
}

// round 10
// speedup vs baseline: 1.6154x; 1.0106x over previous
#include <cuda_runtime.h>
#include <cuda_fp16.h>
#include <math.h>

#define NMAX 100000
#define EMAX 1600000
#define NBLK ((NMAX + 255) / 256)   // 391 <= 512

// Scratch (device globals)
__device__ __align__(16) int    g_degi[NMAX];
__device__ __align__(16) int    g_start[NMAX + 1];
__device__ __align__(16) int    g_bsum[NBLK + 1];
__device__ __align__(16) int    g_boff[NBLK + 1];
__device__ __align__(16) int    g_srcs[EMAX];
__device__ __align__(16) int    g_rank[EMAX];
__device__ __align__(16) int2   g_edge[EMAX];
__device__ __align__(16) float  g_dinv[NMAX];
__device__ __align__(16) float  g_xn[NMAX * 2];
__device__ __align__(16) __half g_h2n[NMAX * 32];
__device__ __align__(16) __half g_na[NMAX * 16];
__device__ __align__(16) __half g_nb[NMAX * 16];
__device__ int g_i64;

// ---------------------------------------------------------------------------
__global__ void k_init(const unsigned* __restrict__ ei_raw, int e, int n) {
    if (blockIdx.x == 0) {
        __shared__ int odd_nonzero;
        if (threadIdx.x == 0) odd_nonzero = 0;
        __syncthreads();
        int i = threadIdx.x;
        if (2 * i + 1 < 2 * e) {
            if (ei_raw[2 * i + 1] != 0u) odd_nonzero = 1;
        }
        __syncthreads();
        if (threadIdx.x == 0) g_i64 = odd_nonzero ? 0 : 1;
    }
    int i = blockIdx.x * blockDim.x + threadIdx.x;
    if (i < n) g_degi[i] = 0;
}

// decode edge_index -> int2 ; histogram in-degree; the atomic's return value
// IS this edge's rank among same-destination edges -> saved for atomic-free scatter.
__global__ void k_prep(const void* __restrict__ ei, int e) {
    int i = blockIdx.x * blockDim.x + threadIdx.x;
    if (i >= e) return;
    int r, c;
    if (g_i64) {
        r = (int)(reinterpret_cast<const long long*>(ei)[i]);
        c = (int)(reinterpret_cast<const long long*>(ei)[(size_t)e + i]);
    } else {
        r = reinterpret_cast<const int*>(ei)[i];
        c = reinterpret_cast<const int*>(ei)[(size_t)e + i];
    }
    g_edge[i] = make_int2(r, c);
    g_rank[i] = atomicAdd(&g_degi[c], 1);
}

// scan phase 1: per-block sums of degi
__global__ void k_scan1(int n) {
    __shared__ int ws[8];
    int lane = threadIdx.x & 31, wid = threadIdx.x >> 5;
    int i = blockIdx.x * 256 + threadIdx.x;
    int v = (i < n) ? g_degi[i] : 0;
#pragma unroll
    for (int o = 16; o > 0; o >>= 1) v += __shfl_down_sync(0xFFFFFFFFu, v, o);
    if (lane == 0) ws[wid] = v;
    __syncthreads();
    if (threadIdx.x == 0) {
        int s = 0;
#pragma unroll
        for (int w = 0; w < 8; w++) s += ws[w];
        g_bsum[blockIdx.x] = s;
    }
}

// scan phase 2: single 512-thread block scans nb block sums.
__global__ void k_scan2(int nb, int n) {
    __shared__ int ws[16];
    int t = threadIdx.x;
    int lane = t & 31, wid = t >> 5;
    int v = (t < nb) ? g_bsum[t] : 0;
    int s = v;
#pragma unroll
    for (int o = 1; o < 32; o <<= 1) {
        int u = __shfl_up_sync(0xFFFFFFFFu, s, o);
        if (lane >= o) s += u;
    }
    if (lane == 31) ws[wid] = s;
    __syncthreads();
    if (wid == 0 && lane < 16) {
        int w = ws[lane];
#pragma unroll
        for (int o = 1; o < 16; o <<= 1) {
            int u = __shfl_up_sync(0x0000FFFFu, w, o);
            if (lane >= o) w += u;
        }
        ws[lane] = w;
    }
    __syncthreads();
    int excl = (wid ? ws[wid - 1] : 0) + s - v;
    if (t < nb) g_boff[t] = excl;
    if (t == nb - 1) g_start[n] = excl + v;
}

// scan phase 3 + dinv fused
__global__ void k_scan3(const float* __restrict__ x, int n) {
    __shared__ int ws[8];
    int lane = threadIdx.x & 31, wid = threadIdx.x >> 5;
    int i = blockIdx.x * 256 + threadIdx.x;
    int v = (i < n) ? g_degi[i] : 0;
    int s = v;
#pragma unroll
    for (int o = 1; o < 32; o <<= 1) {
        int t = __shfl_up_sync(0xFFFFFFFFu, s, o);
        if (lane >= o) s += t;
    }
    if (lane == 31) ws[wid] = s;
    __syncthreads();
    if (wid == 0 && lane < 8) {
        int w = ws[lane];
#pragma unroll
        for (int o = 1; o < 8; o <<= 1) {
            int t = __shfl_up_sync(0x000000FFu, w, o);
            if (lane >= o) w += t;
        }
        ws[lane] = w;
    }
    __syncthreads();
    int excl = g_boff[blockIdx.x] + (wid ? ws[wid - 1] : 0) + s - v;
    if (i < n) {
        g_start[i] = excl;
        float di = rsqrtf((float)(v + 1));
        g_dinv[i] = di;
        float2 xv = reinterpret_cast<const float2*>(x)[i];
        reinterpret_cast<float2*>(g_xn)[i] = make_float2(di * xv.x, di * xv.y);
    }
}

// scatter edges into CSR slots — atomic-free (rank computed in k_prep)
__global__ void k_scatter(int e) {
    int i = blockIdx.x * blockDim.x + threadIdx.x;
    if (i >= e) return;
    int2 eg = g_edge[i];
    int slot = g_start[eg.y] + g_rank[i];
    g_srcs[slot] = eg.x;
}

// layer 1 fused: gather xn (unroll-4), GEMV, write fp16 h2n
__global__ void k_layer1(const float* __restrict__ W1,  // [2,64]
                         const float* __restrict__ b1,  // [64]
                         const float* __restrict__ W2,  // [64,32]
                         int n) {
    __shared__ float sW1[128];
    __shared__ float sb1[64];
    __shared__ float sW2[2048];
    int t = threadIdx.x;
    for (int i = t; i < 128; i += blockDim.x) sW1[i] = W1[i];
    for (int i = t; i < 64; i += blockDim.x) sb1[i] = b1[i];
    for (int i = t; i < 2048; i += blockDim.x) sW2[i] = W2[i];
    __syncthreads();

    int nn = blockIdx.x * blockDim.x + t;
    if (nn >= n) return;
    int s0 = g_start[nn], s1 = g_start[nn + 1];
    float a0 = 0.0f, a1 = 0.0f;
    int j = s0;
    for (; j + 4 <= s1; j += 4) {
        int r0 = g_srcs[j], r1 = g_srcs[j + 1], r2 = g_srcs[j + 2], r3 = g_srcs[j + 3];
        float2 v0 = reinterpret_cast<const float2*>(g_xn)[r0];
        float2 v1 = reinterpret_cast<const float2*>(g_xn)[r1];
        float2 v2 = reinterpret_cast<const float2*>(g_xn)[r2];
        float2 v3 = reinterpret_cast<const float2*>(g_xn)[r3];
        a0 += (v0.x + v1.x) + (v2.x + v3.x);
        a1 += (v0.y + v1.y) + (v2.y + v3.y);
    }
    for (; j < s1; j++) {
        float2 v = reinterpret_cast<const float2*>(g_xn)[g_srcs[j]];
        a0 += v.x; a1 += v.y;
    }
    float di = g_dinv[nn];
    float2 xv = reinterpret_cast<const float2*>(g_xn)[nn];
    float v0 = di * (a0 + xv.x);
    float v1 = di * (a1 + xv.y);

    float acc[32];
#pragma unroll
    for (int k = 0; k < 32; k++) acc[k] = 0.0f;
#pragma unroll 4
    for (int jj = 0; jj < 64; jj++) {
        float h = fmaxf(fmaf(v0, sW1[jj], fmaf(v1, sW1[64 + jj], sb1[jj])), 0.0f);
#pragma unroll
        for (int k = 0; k < 32; k++) acc[k] = fmaf(h, sW2[jj * 32 + k], acc[k]);
    }

    __half2 hp[16];
#pragma unroll
    for (int k = 0; k < 16; k++)
        hp[k] = __floats2half2_rn(di * acc[2 * k], di * acc[2 * k + 1]);
    uint4* o = reinterpret_cast<uint4*>(g_h2n + (size_t)nn * 32);
    const uint4* src = reinterpret_cast<const uint4*>(hp);
#pragma unroll
    for (int k = 0; k < 4; k++) o[k] = src[k];
}

__device__ __forceinline__ void acc_slice(float* acc, uint4 raw) {
    const __half2* hh = reinterpret_cast<const __half2*>(&raw);
#pragma unroll
    for (int k = 0; k < 4; k++) {
        float2 f = __half22float2(hh[k]);
        acc[2 * k] += f.x; acc[2 * k + 1] += f.y;
    }
}

// layer 2 fused, 4 threads/node, gather unroll-2
__global__ void k_layer2(const float* __restrict__ mW1,  // [65,16]
                         const float* __restrict__ b2,   // [32]
                         int n) {
    __shared__ float sAB[1024];
    __shared__ float sb2[32];
    __shared__ float sh[64 * 32];
    int t = threadIdx.x;
    for (int idx = t; idx < 1024; idx += blockDim.x) {
        int k = idx >> 5, i = idx & 31;
        sAB[idx] = (i < 16) ? mW1[k * 16 + i] : mW1[(32 + k) * 16 + (i - 16)];
    }
    for (int i = t; i < 32; i += blockDim.x) sb2[i] = b2[i];
    __syncthreads();

    int local = t >> 2;
    int p = t & 3;
    int nn = blockIdx.x * 64 + local;
    bool active = (nn < n);

    if (active) {
        int s0 = g_start[nn], s1 = g_start[nn + 1];
        float acc[8];
        {
            uint4 raw = reinterpret_cast<const uint4*>(g_h2n + (size_t)nn * 32)[p];
            const __half2* hh = reinterpret_cast<const __half2*>(&raw);
#pragma unroll
            for (int k = 0; k < 4; k++) {
                float2 f = __half22float2(hh[k]);
                acc[2 * k] = f.x; acc[2 * k + 1] = f.y;
            }
        }
        int j = s0;
        for (; j + 2 <= s1; j += 2) {
            int r0 = g_srcs[j], r1 = g_srcs[j + 1];
            uint4 w0 = reinterpret_cast<const uint4*>(g_h2n + (size_t)r0 * 32)[p];
            uint4 w1 = reinterpret_cast<const uint4*>(g_h2n + (size_t)r1 * 32)[p];
            acc_slice(acc, w0);
            acc_slice(acc, w1);
        }
        if (j < s1) {
            int r0 = g_srcs[j];
            acc_slice(acc, reinterpret_cast<const uint4*>(g_h2n + (size_t)r0 * 32)[p]);
        }
        float di = g_dinv[nn];
#pragma unroll
        for (int k = 0; k < 8; k++)
            sh[local * 32 + 8 * p + k] = fmaxf(fmaf(di, acc[k], sb2[8 * p + k]), 0.0f);
    }
    __syncthreads();

    if (active) {
        float o8[8];
#pragma unroll
        for (int i = 0; i < 8; i++) o8[i] = 0.0f;
        const float* hrow = sh + local * 32;
#pragma unroll 8
        for (int k = 0; k < 32; k++) {
            float h = hrow[k];
            const float* w = sAB + k * 32 + 8 * p;
#pragma unroll
            for (int i = 0; i < 8; i++) o8[i] = fmaf(h, w[i], o8[i]);
        }
        __half2 hp[4];
#pragma unroll
        for (int k = 0; k < 4; k++)
            hp[k] = __floats2half2_rn(o8[2 * k], o8[2 * k + 1]);
        __half* base = (p < 2) ? (g_na + (size_t)nn * 16 + 8 * p)
                               : (g_nb + (size_t)nn * 16 + 8 * (p - 2));
        *reinterpret_cast<uint4*>(base) = *reinterpret_cast<const uint4*>(hp);
    }
}

// per edge: hid = relu(na[r] + nb[c] + attr*mW1[64] + mb1); out = sigmoid(hid@mW2 + mb2)
__global__ void k_edge(const float* __restrict__ ea,
                       const float* __restrict__ mW1,
                       const float* __restrict__ mb1,
                       const float* __restrict__ mW2,
                       const float* __restrict__ mb2,
                       float* __restrict__ out, int e) {
    __shared__ float sw64[16], smb1[16], smw2[16];
    __shared__ float smb2;
    int t = threadIdx.x;
    if (t < 16) {
        sw64[t] = mW1[64 * 16 + t];
        smb1[t] = mb1[t];
        smw2[t] = mW2[t];
    }
    if (t == 0) smb2 = mb2[0];
    __syncthreads();

    int i = blockIdx.x * blockDim.x + t;
    if (i >= e) return;
    int2 eg = g_edge[i];
    float attr = ea[i];

    const uint4* pa = reinterpret_cast<const uint4*>(g_na + (size_t)eg.x * 16);
    const uint4* pb = reinterpret_cast<const uint4*>(g_nb + (size_t)eg.y * 16);
    uint4 ra0 = pa[0], ra1 = pa[1];
    uint4 rb0 = pb[0], rb1 = pb[1];

    float s = 0.0f;
    const __half2* ha = reinterpret_cast<const __half2*>(&ra0);
    const __half2* hb = reinterpret_cast<const __half2*>(&rb0);
#pragma unroll
    for (int q = 0; q < 4; q++) {
        float2 av = __half22float2(ha[q]);
        float2 bv = __half22float2(hb[q]);
        float h;
        h = fmaxf(av.x + bv.x + fmaf(attr, sw64[2 * q], smb1[2 * q]), 0.0f);
        s = fmaf(h, smw2[2 * q], s);
        h = fmaxf(av.y + bv.y + fmaf(attr, sw64[2 * q + 1], smb1[2 * q + 1]), 0.0f);
        s = fmaf(h, smw2[2 * q + 1], s);
    }
    const __half2* ha1 = reinterpret_cast<const __half2*>(&ra1);
    const __half2* hb1 = reinterpret_cast<const __half2*>(&rb1);
#pragma unroll
    for (int q = 0; q < 4; q++) {
        float2 av = __half22float2(ha1[q]);
        float2 bv = __half22float2(hb1[q]);
        float h;
        h = fmaxf(av.x + bv.x + fmaf(attr, sw64[8 + 2 * q], smb1[8 + 2 * q]), 0.0f);
        s = fmaf(h, smw2[8 + 2 * q], s);
        h = fmaxf(av.y + bv.y + fmaf(attr, sw64[8 + 2 * q + 1], smb1[8 + 2 * q + 1]), 0.0f);
        s = fmaf(h, smw2[8 + 2 * q + 1], s);
    }
    float z = s + smb2;
    out[i] = 1.0f / (1.0f + __expf(-z));
}

// ---------------------------------------------------------------------------
extern "C" void kernel_launch(void* const* d_in, const int* in_sizes, int n_in,
                              void* d_out, int out_size) {
    const float* x = (const float*)d_in[0];
    const void* ei = d_in[1];
    const float* ea = (const float*)d_in[2];

    int base = (in_sizes[3] == 128) ? 3 : 4;
    const float* W1 = (const float*)d_in[base + 0];
    const float* b1 = (const float*)d_in[base + 1];
    const float* W2 = (const float*)d_in[base + 2];
    const float* b2 = (const float*)d_in[base + 3];
    const float* mW1 = (const float*)d_in[base + 4];
    const float* mb1 = (const float*)d_in[base + 5];
    const float* mW2 = (const float*)d_in[base + 6];
    const float* mb2 = (const float*)d_in[base + 7];

    int n = in_sizes[0] / 2;
    int e = in_sizes[1] / 2;
    float* out = (float*)d_out;

    const int B = 256;
    int gn = (n + B - 1) / B;
    int ge = (e + B - 1) / B;
    int gn4 = (n + 63) / 64;

    k_init<<<gn, B>>>((const unsigned*)ei, e, n);
    k_prep<<<ge, B>>>(ei, e);
    k_scan1<<<gn, B>>>(n);
    k_scan2<<<1, 512>>>(gn, n);
    k_scan3<<<gn, B>>>(x, n);
    k_scatter<<<ge, B>>>(e);
    k_layer1<<<gn, B>>>(W1, b1, W2, n);
    k_layer2<<<gn4, B>>>(mW1, b2, n);
    k_edge<<<ge, B>>>(ea, mW1, mb1, mW2, mb2, out, e);
}

// round 11
// speedup vs baseline: 1.6522x; 1.0228x over previous
#include <cuda_runtime.h>
#include <cuda_fp16.h>
#include <math.h>

#define NMAX 100000
#define EMAX 1600000
#define NBLK ((NMAX + 255) / 256)   // 391

// Scratch (device globals)
__device__ __align__(16) int                g_degi[NMAX];
__device__ __align__(16) int                g_start[NMAX + 1];
__device__ __align__(16) int                g_bsum[NBLK + 1];
__device__ __align__(16) int                g_srcs[EMAX];
__device__ __align__(16) unsigned long long g_edge[EMAX];  // r:17 | c:17<<17 | rank<<34
__device__ __align__(16) float              g_dinv[NMAX];
__device__ __align__(16) float              g_xn[NMAX * 2];
__device__ __align__(16) __half             g_h2n[NMAX * 32];
__device__ __align__(16) __half             g_na[NMAX * 16];
__device__ __align__(16) __half             g_nb[NMAX * 16];
__device__ int g_i64;

// ---------------------------------------------------------------------------
__global__ void k_init(const unsigned* __restrict__ ei_raw, int e, int n) {
    if (blockIdx.x == 0) {
        __shared__ int odd_nonzero;
        if (threadIdx.x == 0) odd_nonzero = 0;
        __syncthreads();
        int i = threadIdx.x;
        if (2 * i + 1 < 2 * e) {
            if (ei_raw[2 * i + 1] != 0u) odd_nonzero = 1;
        }
        __syncthreads();
        if (threadIdx.x == 0) {
            g_i64 = odd_nonzero ? 0 : 1;
            g_start[n] = e;            // total degree (excl self) is just e
        }
    }
    int i = blockIdx.x * blockDim.x + threadIdx.x;
    if (i < n) g_degi[i] = 0;
}

// decode edge_index; histogram in-degree; pack (r, c, rank) into u64.
__global__ void k_prep(const void* __restrict__ ei, int e) {
    int i = blockIdx.x * blockDim.x + threadIdx.x;
    if (i >= e) return;
    unsigned r, c;
    if (g_i64) {
        r = (unsigned)(reinterpret_cast<const long long*>(ei)[i]);
        c = (unsigned)(reinterpret_cast<const long long*>(ei)[(size_t)e + i]);
    } else {
        r = (unsigned)reinterpret_cast<const int*>(ei)[i];
        c = (unsigned)reinterpret_cast<const int*>(ei)[(size_t)e + i];
    }
    unsigned rank = (unsigned)atomicAdd(&g_degi[c], 1);
    g_edge[i] = (unsigned long long)r | ((unsigned long long)c << 17)
              | ((unsigned long long)rank << 34);
}

// scan phase 1: per-block sums of degi
__global__ void k_scan1(int n) {
    __shared__ int ws[8];
    int lane = threadIdx.x & 31, wid = threadIdx.x >> 5;
    int i = blockIdx.x * 256 + threadIdx.x;
    int v = (i < n) ? g_degi[i] : 0;
#pragma unroll
    for (int o = 16; o > 0; o >>= 1) v += __shfl_down_sync(0xFFFFFFFFu, v, o);
    if (lane == 0) ws[wid] = v;
    __syncthreads();
    if (threadIdx.x == 0) {
        int s = 0;
#pragma unroll
        for (int w = 0; w < 8; w++) s += ws[w];
        g_bsum[blockIdx.x] = s;
    }
}

// scan phase 2+3 fused: each block reduces bsum[0..b) for its own offset,
// then local exclusive scan; writes start, dinv, xn.
__global__ void k_scan(const float* __restrict__ x, int n) {
    __shared__ int ws[8];
    __shared__ int s_boff;
    int t = threadIdx.x;
    int lane = t & 31, wid = t >> 5;
    int b = blockIdx.x;

    // block offset = sum_{j<b} bsum[j]  (reduction, 256 threads x 2 values)
    {
        int v = 0;
        if (t < b) v += g_bsum[t];
        if (t + 256 < b) v += g_bsum[t + 256];
#pragma unroll
        for (int o = 16; o > 0; o >>= 1) v += __shfl_down_sync(0xFFFFFFFFu, v, o);
        if (lane == 0) ws[wid] = v;
        __syncthreads();
        if (t == 0) {
            int s = 0;
#pragma unroll
            for (int w = 0; w < 8; w++) s += ws[w];
            s_boff = s;
        }
        __syncthreads();
    }

    int i = b * 256 + t;
    int v = (i < n) ? g_degi[i] : 0;
    int s = v;
#pragma unroll
    for (int o = 1; o < 32; o <<= 1) {
        int u = __shfl_up_sync(0xFFFFFFFFu, s, o);
        if (lane >= o) s += u;
    }
    if (lane == 31) ws[wid] = s;
    __syncthreads();
    if (wid == 0 && lane < 8) {
        int w = ws[lane];
#pragma unroll
        for (int o = 1; o < 8; o <<= 1) {
            int u = __shfl_up_sync(0x000000FFu, w, o);
            if (lane >= o) w += u;
        }
        ws[lane] = w;
    }
    __syncthreads();
    int excl = s_boff + (wid ? ws[wid - 1] : 0) + s - v;
    if (i < n) {
        g_start[i] = excl;
        float di = rsqrtf((float)(v + 1));
        g_dinv[i] = di;
        float2 xv = reinterpret_cast<const float2*>(x)[i];
        reinterpret_cast<float2*>(g_xn)[i] = make_float2(di * xv.x, di * xv.y);
    }
}

// scatter edges into CSR slots — atomic-free
__global__ void k_scatter(int e) {
    int i = blockIdx.x * blockDim.x + threadIdx.x;
    if (i >= e) return;
    unsigned long long v = g_edge[i];
    int r = (int)(v & 0x1FFFFu);
    int c = (int)((v >> 17) & 0x1FFFFu);
    int rank = (int)(v >> 34);
    g_srcs[g_start[c] + rank] = r;
}

// layer 1 fused: gather xn (unroll-4), GEMV, write fp16 h2n
__global__ void k_layer1(const float* __restrict__ W1,  // [2,64]
                         const float* __restrict__ b1,  // [64]
                         const float* __restrict__ W2,  // [64,32]
                         int n) {
    __shared__ float sW1[128];
    __shared__ float sb1[64];
    __shared__ float sW2[2048];
    int t = threadIdx.x;
    for (int i = t; i < 128; i += blockDim.x) sW1[i] = W1[i];
    for (int i = t; i < 64; i += blockDim.x) sb1[i] = b1[i];
    for (int i = t; i < 2048; i += blockDim.x) sW2[i] = W2[i];
    __syncthreads();

    int nn = blockIdx.x * blockDim.x + t;
    if (nn >= n) return;
    int s0 = g_start[nn], s1 = g_start[nn + 1];
    float a0 = 0.0f, a1 = 0.0f;
    int j = s0;
    for (; j + 4 <= s1; j += 4) {
        int r0 = g_srcs[j], r1 = g_srcs[j + 1], r2 = g_srcs[j + 2], r3 = g_srcs[j + 3];
        float2 v0 = reinterpret_cast<const float2*>(g_xn)[r0];
        float2 v1 = reinterpret_cast<const float2*>(g_xn)[r1];
        float2 v2 = reinterpret_cast<const float2*>(g_xn)[r2];
        float2 v3 = reinterpret_cast<const float2*>(g_xn)[r3];
        a0 += (v0.x + v1.x) + (v2.x + v3.x);
        a1 += (v0.y + v1.y) + (v2.y + v3.y);
    }
    for (; j < s1; j++) {
        float2 v = reinterpret_cast<const float2*>(g_xn)[g_srcs[j]];
        a0 += v.x; a1 += v.y;
    }
    float di = g_dinv[nn];
    float2 xv = reinterpret_cast<const float2*>(g_xn)[nn];
    float v0 = di * (a0 + xv.x);
    float v1 = di * (a1 + xv.y);

    float acc[32];
#pragma unroll
    for (int k = 0; k < 32; k++) acc[k] = 0.0f;
#pragma unroll 4
    for (int jj = 0; jj < 64; jj++) {
        float h = fmaxf(fmaf(v0, sW1[jj], fmaf(v1, sW1[64 + jj], sb1[jj])), 0.0f);
#pragma unroll
        for (int k = 0; k < 32; k++) acc[k] = fmaf(h, sW2[jj * 32 + k], acc[k]);
    }

    __half2 hp[16];
#pragma unroll
    for (int k = 0; k < 16; k++)
        hp[k] = __floats2half2_rn(di * acc[2 * k], di * acc[2 * k + 1]);
    uint4* o = reinterpret_cast<uint4*>(g_h2n + (size_t)nn * 32);
    const uint4* src = reinterpret_cast<const uint4*>(hp);
#pragma unroll
    for (int k = 0; k < 4; k++) o[k] = src[k];
}

__device__ __forceinline__ void acc_slice(float* acc, uint4 raw) {
    const __half2* hh = reinterpret_cast<const __half2*>(&raw);
#pragma unroll
    for (int k = 0; k < 4; k++) {
        float2 f = __half22float2(hh[k]);
        acc[2 * k] += f.x; acc[2 * k + 1] += f.y;
    }
}

// layer 2 fused, 4 threads/node, gather unroll-2
__global__ void k_layer2(const float* __restrict__ mW1,  // [65,16]
                         const float* __restrict__ b2,   // [32]
                         int n) {
    __shared__ float sAB[1024];
    __shared__ float sb2[32];
    __shared__ float sh[64 * 32];
    int t = threadIdx.x;
    for (int idx = t; idx < 1024; idx += blockDim.x) {
        int k = idx >> 5, i = idx & 31;
        sAB[idx] = (i < 16) ? mW1[k * 16 + i] : mW1[(32 + k) * 16 + (i - 16)];
    }
    for (int i = t; i < 32; i += blockDim.x) sb2[i] = b2[i];
    __syncthreads();

    int local = t >> 2;
    int p = t & 3;
    int nn = blockIdx.x * 64 + local;
    bool active = (nn < n);

    if (active) {
        int s0 = g_start[nn], s1 = g_start[nn + 1];
        float acc[8];
        {
            uint4 raw = reinterpret_cast<const uint4*>(g_h2n + (size_t)nn * 32)[p];
            const __half2* hh = reinterpret_cast<const __half2*>(&raw);
#pragma unroll
            for (int k = 0; k < 4; k++) {
                float2 f = __half22float2(hh[k]);
                acc[2 * k] = f.x; acc[2 * k + 1] = f.y;
            }
        }
        int j = s0;
        for (; j + 2 <= s1; j += 2) {
            int r0 = g_srcs[j], r1 = g_srcs[j + 1];
            uint4 w0 = reinterpret_cast<const uint4*>(g_h2n + (size_t)r0 * 32)[p];
            uint4 w1 = reinterpret_cast<const uint4*>(g_h2n + (size_t)r1 * 32)[p];
            acc_slice(acc, w0);
            acc_slice(acc, w1);
        }
        if (j < s1) {
            int r0 = g_srcs[j];
            acc_slice(acc, reinterpret_cast<const uint4*>(g_h2n + (size_t)r0 * 32)[p]);
        }
        float di = g_dinv[nn];
#pragma unroll
        for (int k = 0; k < 8; k++)
            sh[local * 32 + 8 * p + k] = fmaxf(fmaf(di, acc[k], sb2[8 * p + k]), 0.0f);
    }
    __syncthreads();

    if (active) {
        float o8[8];
#pragma unroll
        for (int i = 0; i < 8; i++) o8[i] = 0.0f;
        const float* hrow = sh + local * 32;
#pragma unroll 8
        for (int k = 0; k < 32; k++) {
            float h = hrow[k];
            const float* w = sAB + k * 32 + 8 * p;
#pragma unroll
            for (int i = 0; i < 8; i++) o8[i] = fmaf(h, w[i], o8[i]);
        }
        __half2 hp[4];
#pragma unroll
        for (int k = 0; k < 4; k++)
            hp[k] = __floats2half2_rn(o8[2 * k], o8[2 * k + 1]);
        __half* base = (p < 2) ? (g_na + (size_t)nn * 16 + 8 * p)
                               : (g_nb + (size_t)nn * 16 + 8 * (p - 2));
        *reinterpret_cast<uint4*>(base) = *reinterpret_cast<const uint4*>(hp);
    }
}

// per edge: hid = relu(na[r] + nb[c] + attr*mW1[64] + mb1); out = sigmoid(hid@mW2 + mb2)
__global__ void k_edge(const float* __restrict__ ea,
                       const float* __restrict__ mW1,
                       const float* __restrict__ mb1,
                       const float* __restrict__ mW2,
                       const float* __restrict__ mb2,
                       float* __restrict__ out, int e) {
    __shared__ float sw64[16], smb1[16], smw2[16];
    __shared__ float smb2;
    int t = threadIdx.x;
    if (t < 16) {
        sw64[t] = mW1[64 * 16 + t];
        smb1[t] = mb1[t];
        smw2[t] = mW2[t];
    }
    if (t == 0) smb2 = mb2[0];
    __syncthreads();

    int i = blockIdx.x * blockDim.x + t;
    if (i >= e) return;
    unsigned long long v = g_edge[i];
    int r = (int)(v & 0x1FFFFu);
    int c = (int)((v >> 17) & 0x1FFFFu);
    float attr = ea[i];

    const uint4* pa = reinterpret_cast<const uint4*>(g_na + (size_t)r * 16);
    const uint4* pb = reinterpret_cast<const uint4*>(g_nb + (size_t)c * 16);
    uint4 ra0 = pa[0], ra1 = pa[1];
    uint4 rb0 = pb[0], rb1 = pb[1];

    float s = 0.0f;
    const __half2* ha = reinterpret_cast<const __half2*>(&ra0);
    const __half2* hb = reinterpret_cast<const __half2*>(&rb0);
#pragma unroll
    for (int q = 0; q < 4; q++) {
        float2 av = __half22float2(ha[q]);
        float2 bv = __half22float2(hb[q]);
        float h;
        h = fmaxf(av.x + bv.x + fmaf(attr, sw64[2 * q], smb1[2 * q]), 0.0f);
        s = fmaf(h, smw2[2 * q], s);
        h = fmaxf(av.y + bv.y + fmaf(attr, sw64[2 * q + 1], smb1[2 * q + 1]), 0.0f);
        s = fmaf(h, smw2[2 * q + 1], s);
    }
    const __half2* ha1 = reinterpret_cast<const __half2*>(&ra1);
    const __half2* hb1 = reinterpret_cast<const __half2*>(&rb1);
#pragma unroll
    for (int q = 0; q < 4; q++) {
        float2 av = __half22float2(ha1[q]);
        float2 bv = __half22float2(hb1[q]);
        float h;
        h = fmaxf(av.x + bv.x + fmaf(attr, sw64[8 + 2 * q], smb1[8 + 2 * q]), 0.0f);
        s = fmaf(h, smw2[8 + 2 * q], s);
        h = fmaxf(av.y + bv.y + fmaf(attr, sw64[8 + 2 * q + 1], smb1[8 + 2 * q + 1]), 0.0f);
        s = fmaf(h, smw2[8 + 2 * q + 1], s);
    }
    float z = s + smb2;
    out[i] = 1.0f / (1.0f + __expf(-z));
}

// ---------------------------------------------------------------------------
extern "C" void kernel_launch(void* const* d_in, const int* in_sizes, int n_in,
                              void* d_out, int out_size) {
    const float* x = (const float*)d_in[0];
    const void* ei = d_in[1];
    const float* ea = (const float*)d_in[2];

    int base = (in_sizes[3] == 128) ? 3 : 4;
    const float* W1 = (const float*)d_in[base + 0];
    const float* b1 = (const float*)d_in[base + 1];
    const float* W2 = (const float*)d_in[base + 2];
    const float* b2 = (const float*)d_in[base + 3];
    const float* mW1 = (const float*)d_in[base + 4];
    const float* mb1 = (const float*)d_in[base + 5];
    const float* mW2 = (const float*)d_in[base + 6];
    const float* mb2 = (const float*)d_in[base + 7];

    int n = in_sizes[0] / 2;
    int e = in_sizes[1] / 2;
    float* out = (float*)d_out;

    const int B = 256;
    int gn = (n + B - 1) / B;
    int ge = (e + B - 1) / B;
    int gn4 = (n + 63) / 64;

    k_init<<<gn, B>>>((const unsigned*)ei, e, n);
    k_prep<<<ge, B>>>(ei, e);
    k_scan1<<<gn, B>>>(n);
    k_scan<<<gn, B>>>(x, n);
    k_scatter<<<ge, B>>>(e);
    k_layer1<<<gn, B>>>(W1, b1, W2, n);
    k_layer2<<<gn4, B>>>(mW1, b2, n);
    k_edge<<<ge, B>>>(ea, mW1, mb1, mW2, mb2, out, e);
}